// round 1
// baseline (speedup 1.0000x reference)
#include <cuda_runtime.h>
#include <math.h>

#define B_   32
#define C_   256
#define H_   56
#define W_   56
#define E_   4
#define O_   256
#define HID_ 64
#define NPIX (H_*W_)       // 3136
#define KDIM (C_*9)        // 2304
#define WPERB (O_*C_*9)    // 589824

// Scratch (device globals: allowed; no runtime allocation)
__device__ float g_routing[B_*E_];
__device__ float g_combined[(size_t)B_*WPERB];   // 75.5 MB

// ---------------------------------------------------------------------------
// Kernel 1: routing = softmax(relu(mean(x) @ rw1.T + rb1) @ rw2.T + rb2)
// One block per sample, 256 threads (8 warps).
// ---------------------------------------------------------------------------
__global__ void routing_kernel(const float* __restrict__ x,
                               const float* __restrict__ rw1,
                               const float* __restrict__ rb1,
                               const float* __restrict__ rw2,
                               const float* __restrict__ rb2) {
    const int b    = blockIdx.x;
    const int tid  = threadIdx.x;
    const int warp = tid >> 5;
    const int lane = tid & 31;

    __shared__ float pooled[C_];
    __shared__ float hid[HID_];
    __shared__ float logits[E_];

    const float* xb = x + (size_t)b * C_ * NPIX;
    for (int c = warp; c < C_; c += 8) {
        const float* xc = xb + (size_t)c * NPIX;
        float s = 0.f;
        for (int i = lane; i < NPIX; i += 32) s += xc[i];
        #pragma unroll
        for (int o = 16; o; o >>= 1) s += __shfl_xor_sync(0xffffffffu, s, o);
        if (lane == 0) pooled[c] = s * (1.0f / (float)NPIX);
    }
    __syncthreads();

    if (tid < HID_) {
        float s = rb1[tid];
        const float* w = rw1 + tid * C_;
        #pragma unroll 8
        for (int c = 0; c < C_; c++) s = fmaf(w[c], pooled[c], s);
        hid[tid] = fmaxf(s, 0.f);
    }
    __syncthreads();

    if (tid < E_) {
        float s = rb2[tid];
        const float* w = rw2 + tid * HID_;
        #pragma unroll 8
        for (int h = 0; h < HID_; h++) s = fmaf(w[h], hid[h], s);
        logits[tid] = s;
    }
    __syncthreads();

    if (tid == 0) {
        float m = logits[0];
        #pragma unroll
        for (int e = 1; e < E_; e++) m = fmaxf(m, logits[e]);
        float ex[E_], sum = 0.f;
        #pragma unroll
        for (int e = 0; e < E_; e++) { ex[e] = expf(logits[e] - m); sum += ex[e]; }
        float inv = 1.0f / sum;
        #pragma unroll
        for (int e = 0; e < E_; e++) g_routing[b*E_ + e] = ex[e] * inv;
    }
}

// ---------------------------------------------------------------------------
// Kernel 2: combined[b] = sum_e routing[b,e] * experts[e]   (float4 streams)
// ---------------------------------------------------------------------------
__global__ void __launch_bounds__(256) combine_kernel(const float* __restrict__ experts) {
    const int b = blockIdx.y;
    const int i = blockIdx.x * blockDim.x + threadIdx.x;   // float4 index
    if (i >= WPERB/4) return;

    const float r0 = g_routing[b*E_+0];
    const float r1 = g_routing[b*E_+1];
    const float r2 = g_routing[b*E_+2];
    const float r3 = g_routing[b*E_+3];

    const float4* e0 = (const float4*)(experts + (size_t)0*WPERB);
    const float4* e1 = (const float4*)(experts + (size_t)1*WPERB);
    const float4* e2 = (const float4*)(experts + (size_t)2*WPERB);
    const float4* e3 = (const float4*)(experts + (size_t)3*WPERB);

    float4 a = e0[i], c = e1[i], d = e2[i], f = e3[i];
    float4 o;
    o.x = r0*a.x + r1*c.x + r2*d.x + r3*f.x;
    o.y = r0*a.y + r1*c.y + r2*d.y + r3*f.y;
    o.z = r0*a.z + r1*c.z + r2*d.z + r3*f.z;
    o.w = r0*a.w + r1*c.w + r2*d.w + r3*f.w;

    ((float4*)(g_combined + (size_t)b * WPERB))[i] = o;
}

// ---------------------------------------------------------------------------
// Kernel 3: per-sample implicit-GEMM conv.
//   out[b][m][n] = sum_k A[b][m][k] * B[b][k][n]
//   A = combined weights [O=256, KDIM=2304]
//   B = im2col(x)        [KDIM, NPIX=3136]  (built on the fly)
// Tiling: BM=128, BN=128, BK=16; 256 threads; 8x8 microtile per thread.
// ---------------------------------------------------------------------------
__global__ void __launch_bounds__(256) conv_kernel(const float* __restrict__ x,
                                                   float* __restrict__ out) {
    const int b     = blockIdx.z;
    const int mBase = blockIdx.y * 128;
    const int nBase = blockIdx.x * 128;

    const float* A  = g_combined + (size_t)b * WPERB;
    const float* xb = x + (size_t)b * C_ * NPIX;

    __shared__ float As[16][132];   // [k][m], pad 132 -> conflict-free transpose store
    __shared__ float Bs[16][128];   // [k][n]

    const int tid = threadIdx.x;
    const int tx  = tid & 15;       // n-direction
    const int ty  = tid >> 4;       // m-direction

    // B-loader mapping: 16 k-rows x (16 threads * 8 n each)
    const int kIdx = tid >> 4;
    const int nOff = (tid & 15) * 8;

    float acc[8][8];
    #pragma unroll
    for (int i = 0; i < 8; i++)
        #pragma unroll
        for (int j = 0; j < 8; j++) acc[i][j] = 0.f;

    for (int kt = 0; kt < KDIM/16; kt++) {
        const int kBase = kt * 16;

        // ---- load A tile (128 x 16) : 512 float4, 2 per thread, transpose ----
        #pragma unroll
        for (int it = 0; it < 2; it++) {
            int j    = tid + it*256;
            int col4 = j & 3;
            int row  = j >> 2;
            float4 v = *(const float4*)(A + (size_t)(mBase + row)*KDIM + kBase + col4*4);
            As[col4*4+0][row] = v.x;
            As[col4*4+1][row] = v.y;
            As[col4*4+2][row] = v.z;
            As[col4*4+3][row] = v.w;
        }

        // ---- load B tile (16 x 128) with on-the-fly im2col ----
        {
            const int k   = kBase + kIdx;
            const int c   = k / 9;
            const int rem = k - c*9;
            const int ky  = rem / 3;
            const int kx  = rem - ky*3;
            const float* xc = xb + (size_t)c * NPIX;
            #pragma unroll
            for (int u = 0; u < 8; u++) {
                int n = nBase + nOff + u;
                float v = 0.f;
                if (n < NPIX) {
                    int ny = n / 56;
                    int nx = n - ny*56;
                    int iy = ny + ky - 1;
                    int ix = nx + kx - 1;
                    if (iy >= 0 && iy < 56 && ix >= 0 && ix < 56)
                        v = xc[iy*56 + ix];
                }
                Bs[kIdx][nOff + u] = v;
            }
        }
        __syncthreads();

        // ---- FMA mainloop ----
        #pragma unroll
        for (int kk = 0; kk < 16; kk++) {
            float a[8], bb[8];
            *(float4*)&a[0]  = *(const float4*)&As[kk][ty*8];
            *(float4*)&a[4]  = *(const float4*)&As[kk][ty*8+4];
            *(float4*)&bb[0] = *(const float4*)&Bs[kk][tx*8];
            *(float4*)&bb[4] = *(const float4*)&Bs[kk][tx*8+4];
            #pragma unroll
            for (int i = 0; i < 8; i++)
                #pragma unroll
                for (int j = 0; j < 8; j++)
                    acc[i][j] = fmaf(a[i], bb[j], acc[i][j]);
        }
        __syncthreads();
    }

    // ---- epilogue ----
    float* outb = out + (size_t)b * O_ * NPIX;
    const bool fullTile = (nBase + 128 <= NPIX);
    #pragma unroll
    for (int i = 0; i < 8; i++) {
        const int m = mBase + ty*8 + i;
        float* orow = outb + (size_t)m * NPIX;
        if (fullTile) {
            #pragma unroll
            for (int j = 0; j < 8; j += 4) {
                float4 v = make_float4(acc[i][j], acc[i][j+1], acc[i][j+2], acc[i][j+3]);
                *(float4*)(orow + nBase + tx*8 + j) = v;
            }
        } else {
            #pragma unroll
            for (int j = 0; j < 8; j++) {
                int n = nBase + tx*8 + j;
                if (n < NPIX) orow[n] = acc[i][j];
            }
        }
    }
}

// ---------------------------------------------------------------------------
extern "C" void kernel_launch(void* const* d_in, const int* in_sizes, int n_in,
                              void* d_out, int out_size) {
    const float* x       = (const float*)d_in[0];
    const float* experts = (const float*)d_in[1];
    const float* rw1     = (const float*)d_in[2];
    const float* rb1     = (const float*)d_in[3];
    const float* rw2     = (const float*)d_in[4];
    const float* rb2     = (const float*)d_in[5];
    float* out           = (float*)d_out;

    // 1) routing
    routing_kernel<<<B_, 256>>>(x, rw1, rb1, rw2, rb2);

    // 2) weight mixing: WPERB/4 float4 per sample
    {
        dim3 grid((WPERB/4 + 255)/256, B_);
        combine_kernel<<<grid, 256>>>(experts);
    }

    // 3) implicit-GEMM conv: N tiles = ceil(3136/128)=25, M tiles = 2, batch 32
    {
        dim3 grid(25, 2, B_);
        conv_kernel<<<grid, 256>>>(x, out);
    }
}

// round 3
// speedup vs baseline: 2.8340x; 2.8340x over previous
#include <cuda_runtime.h>
#include <cuda_bf16.h>
#include <stdint.h>
#include <math.h>

#define B_   32
#define C_   256
#define HH   56
#define WW   56
#define E_   4
#define O_   256
#define HID_ 64
#define NPIX 3136
#define KDIM 2304
#define WPERB (O_*KDIM)
#define BK   32
#define PADK 36                       // padded k-stride (floats) -> conflict-free frags
#define NKT  (KDIM/BK)                // 72 k-tiles

// ---------------- device scratch (no runtime allocation) ----------------
__device__ float g_routing[B_*E_];
__device__ float g_pooled[B_*C_];
__device__ float g_combined[(size_t)B_*WPERB];   // tf32-rounded mixed weights

// ---------------- helpers ----------------
__device__ __forceinline__ uint32_t f2tf32(float f) {
    uint32_t u;
    asm("cvt.rna.tf32.f32 %0, %1;" : "=r"(u) : "f"(f));
    return u;
}

__device__ __forceinline__ void mma_tf32(float* d, const uint32_t* a, const uint32_t* b) {
    asm volatile(
        "mma.sync.aligned.m16n8k8.row.col.f32.tf32.tf32.f32 "
        "{%0,%1,%2,%3}, {%4,%5,%6,%7}, {%8,%9}, {%0,%1,%2,%3};"
        : "+f"(d[0]), "+f"(d[1]), "+f"(d[2]), "+f"(d[3])
        : "r"(a[0]), "r"(a[1]), "r"(a[2]), "r"(a[3]), "r"(b[0]), "r"(b[1]));
}

// ===========================================================================
// Kernel 1a: per-channel global average pool. grid (C_, B_), 128 threads.
// ===========================================================================
__global__ void __launch_bounds__(128) pool_kernel(const float* __restrict__ x) {
    const int c = blockIdx.x, b = blockIdx.y;
    const int tid = threadIdx.x;
    const float4* xc = (const float4*)(x + ((size_t)b*C_ + c)*NPIX);
    float s = 0.f;
    for (int i = tid; i < NPIX/4; i += 128) { float4 v = xc[i]; s += (v.x+v.y)+(v.z+v.w); }
    #pragma unroll
    for (int o = 16; o; o >>= 1) s += __shfl_xor_sync(0xffffffffu, s, o);
    __shared__ float ws[4];
    if ((tid & 31) == 0) ws[tid >> 5] = s;
    __syncthreads();
    if (tid == 0) g_pooled[b*C_ + c] = (ws[0]+ws[1]+ws[2]+ws[3]) * (1.0f/(float)NPIX);
}

// ===========================================================================
// Kernel 1b: MLP + softmax routing. grid B_, 64 threads.
// ===========================================================================
__global__ void __launch_bounds__(64) mlp_kernel(const float* __restrict__ rw1,
                                                 const float* __restrict__ rb1,
                                                 const float* __restrict__ rw2,
                                                 const float* __restrict__ rb2) {
    const int b = blockIdx.x, t = threadIdx.x;
    __shared__ float pl[C_];
    __shared__ float hid[HID_];
    __shared__ float logits[E_];
    for (int c = t; c < C_; c += 64) pl[c] = g_pooled[b*C_ + c];
    __syncthreads();
    {
        float s = rb1[t];
        const float* w = rw1 + t * C_;
        #pragma unroll 8
        for (int c = 0; c < C_; c++) s = fmaf(w[c], pl[c], s);
        hid[t] = fmaxf(s, 0.f);
    }
    __syncthreads();
    if (t < E_) {
        float s = rb2[t];
        const float* w = rw2 + t * HID_;
        #pragma unroll 8
        for (int h = 0; h < HID_; h++) s = fmaf(w[h], hid[h], s);
        logits[t] = s;
    }
    __syncthreads();
    if (t == 0) {
        float m = logits[0];
        #pragma unroll
        for (int e = 1; e < E_; e++) m = fmaxf(m, logits[e]);
        float ex[E_], sum = 0.f;
        #pragma unroll
        for (int e = 0; e < E_; e++) { ex[e] = expf(logits[e] - m); sum += ex[e]; }
        float inv = 1.0f / sum;
        #pragma unroll
        for (int e = 0; e < E_; e++) g_routing[b*E_ + e] = ex[e] * inv;
    }
}

// ===========================================================================
// Kernel 2: mix experts -> per-sample weights (tf32-rounded fp32).
// ===========================================================================
__global__ void __launch_bounds__(256) combine_kernel(const float* __restrict__ experts) {
    const int b = blockIdx.y;
    const int i = blockIdx.x * 256 + threadIdx.x;     // float4 index
    if (i >= WPERB/4) return;

    const float r0 = g_routing[b*E_+0], r1 = g_routing[b*E_+1];
    const float r2 = g_routing[b*E_+2], r3 = g_routing[b*E_+3];
    float4 a = ((const float4*)(experts + (size_t)0*WPERB))[i];
    float4 c = ((const float4*)(experts + (size_t)1*WPERB))[i];
    float4 d = ((const float4*)(experts + (size_t)2*WPERB))[i];
    float4 f = ((const float4*)(experts + (size_t)3*WPERB))[i];

    uint4 o;
    o.x = f2tf32(r0*a.x + r1*c.x + r2*d.x + r3*f.x);
    o.y = f2tf32(r0*a.y + r1*c.y + r2*d.y + r3*f.y);
    o.z = f2tf32(r0*a.z + r1*c.z + r2*d.z + r3*f.z);
    o.w = f2tf32(r0*a.w + r1*c.w + r2*d.w + r3*f.w);
    ((uint4*)g_combined)[(size_t)b*(WPERB/4) + i] = o;
}

// ===========================================================================
// Kernel 3: TF32 mma.sync implicit-GEMM conv.
//   D[oc 128][px 128] += W[oc][k] * im2col(x)[k][px],  K=2304 in 72 tiles of 32.
//   A (weights) smem [m][k] pad 36; B (im2col) smem [n][k] pad 36.
//   8 warps in 2(m) x 4(n); warp tile 64x32; m16n8k8 fragments.
// ===========================================================================
__global__ void __launch_bounds__(256, 1) conv_mma_kernel(const float* __restrict__ x,
                                                          float* __restrict__ out) {
    extern __shared__ float sm[];
    float* As   = sm;                        // 2 * 128 * 36
    float* Bs   = sm + 2*128*PADK;           // 2 * 128 * 36
    int2*  ktab = (int2*)(sm + 4*128*PADK);  // KDIM entries

    const int tid   = threadIdx.x;
    const int lane  = tid & 31;
    const int warp  = tid >> 5;
    const int nBase = blockIdx.x * 128;
    const int mBase = blockIdx.y * 128;
    const int b     = blockIdx.z;

    const int g  = lane >> 2;      // 0..7
    const int tg = lane & 3;       // 0..3
    const int wm = warp >> 2;      // 0..1
    const int wn = warp & 3;       // 0..3

    // im2col k-table
    for (int k = tid; k < KDIM; k += 256) {
        int c = k / 9, rem = k - 9*c;
        int ky = rem / 3 - 1, kx = rem % 3 - 1;
        ktab[k] = make_int2(c*NPIX + ky*WW + kx, (ky << 16) | (kx & 0xffff));
    }
    __syncthreads();

    const float* Ab = g_combined + (size_t)b * WPERB + (size_t)mBase * KDIM;
    const float* xb = x + (size_t)b * C_ * NPIX;

    // B producer coords: one pixel per thread (nl), 16 strided k's
    const int nl = tid & 127;
    const int kstart = tid >> 7;          // 0 or 1
    const int n = nBase + nl;
    const bool nvalid = (n < NPIX);
    const int ny = n / WW, nx = n - (n / WW) * WW;

    float4 areg[4];
    float  breg[16];

    // ---- staging helpers (inlined) ----
    #define LDG_TILE(kt) do {                                                        \
        const int _k0 = (kt) * BK;                                                   \
        _Pragma("unroll")                                                            \
        for (int i = 0; i < 4; i++) {                                                \
            int idx = tid + i*256, row = idx >> 3, c4 = idx & 7;                     \
            areg[i] = *(const float4*)(Ab + (size_t)row*KDIM + _k0 + c4*4);          \
        }                                                                            \
        _Pragma("unroll")                                                            \
        for (int i = 0; i < 16; i++) {                                               \
            int k = kstart + 2*i;                                                    \
            int2 t = ktab[_k0 + k];                                                  \
            int ky = t.y >> 16, kx = (int)(short)(t.y & 0xffff);                     \
            float v = 0.f;                                                           \
            if (nvalid && (unsigned)(ny + ky) < 56u && (unsigned)(nx + kx) < 56u)    \
                v = __ldg(xb + t.x + n);                                             \
            breg[i] = v;                                                             \
        }                                                                            \
    } while (0)

    #define STS_TILE(s) do {                                                         \
        float* _as = As + (s)*128*PADK;                                              \
        float* _bs = Bs + (s)*128*PADK;                                              \
        _Pragma("unroll")                                                            \
        for (int i = 0; i < 4; i++) {                                                \
            int idx = tid + i*256, row = idx >> 3, c4 = idx & 7;                     \
            *(float4*)(_as + row*PADK + c4*4) = areg[i];                             \
        }                                                                            \
        uint32_t* _bu = (uint32_t*)(_bs + nl*PADK);                                  \
        _Pragma("unroll")                                                            \
        for (int i = 0; i < 16; i++) _bu[kstart + 2*i] = f2tf32(breg[i]);            \
    } while (0)

    float acc[4][4][4];
    #pragma unroll
    for (int mi = 0; mi < 4; mi++)
        #pragma unroll
        for (int ni = 0; ni < 4; ni++)
            #pragma unroll
            for (int q = 0; q < 4; q++) acc[mi][ni][q] = 0.f;

    // prologue
    LDG_TILE(0);
    STS_TILE(0);
    __syncthreads();

    for (int kt = 0; kt < NKT; kt++) {
        const int cur = kt & 1;
        if (kt + 1 < NKT) LDG_TILE(kt + 1);

        const uint32_t* Asw = (const uint32_t*)(As + cur*128*PADK + (wm*64 + g)*PADK);
        const uint32_t* Bsw = (const uint32_t*)(Bs + cur*128*PADK + (wn*32 + g)*PADK);

        #pragma unroll
        for (int ks = 0; ks < 4; ks++) {
            const int kc = ks*8 + tg;
            uint32_t afr[4][4];
            #pragma unroll
            for (int mi = 0; mi < 4; mi++) {
                const uint32_t* p = Asw + mi*16*PADK + kc;
                afr[mi][0] = p[0];
                afr[mi][2] = p[4];
                afr[mi][1] = p[8*PADK];
                afr[mi][3] = p[8*PADK + 4];
            }
            uint32_t bfr[4][2];
            #pragma unroll
            for (int ni = 0; ni < 4; ni++) {
                const uint32_t* q = Bsw + ni*8*PADK + kc;
                bfr[ni][0] = q[0];
                bfr[ni][1] = q[4];
            }
            #pragma unroll
            for (int mi = 0; mi < 4; mi++)
                #pragma unroll
                for (int ni = 0; ni < 4; ni++)
                    mma_tf32(acc[mi][ni], afr[mi], bfr[ni]);
        }

        if (kt + 1 < NKT) STS_TILE(cur ^ 1);
        __syncthreads();
    }

    // ---- epilogue ----
    float* ob = out + (size_t)b * O_ * NPIX;
    #pragma unroll
    for (int mi = 0; mi < 4; mi++) {
        const int r0 = mBase + wm*64 + mi*16 + g;
        #pragma unroll
        for (int ni = 0; ni < 4; ni++) {
            const int cb = nBase + wn*32 + ni*8 + 2*tg;
            if (cb < NPIX) {
                *(float2*)(ob + (size_t)r0*NPIX + cb)     = make_float2(acc[mi][ni][0], acc[mi][ni][1]);
                *(float2*)(ob + (size_t)(r0+8)*NPIX + cb) = make_float2(acc[mi][ni][2], acc[mi][ni][3]);
            }
        }
    }
    #undef LDG_TILE
    #undef STS_TILE
}

#define CONV_SMEM (4*128*PADK*4 + KDIM*8)   // 73728 + 18432 = 92160 B

// ===========================================================================
extern "C" void kernel_launch(void* const* d_in, const int* in_sizes, int n_in,
                              void* d_out, int out_size) {
    const float* x       = (const float*)d_in[0];
    const float* experts = (const float*)d_in[1];
    const float* rw1     = (const float*)d_in[2];
    const float* rb1     = (const float*)d_in[3];
    const float* rw2     = (const float*)d_in[4];
    const float* rb2     = (const float*)d_in[5];
    float* out           = (float*)d_out;

    static bool attr_set = false;
    if (!attr_set) {
        cudaFuncSetAttribute(conv_mma_kernel,
                             cudaFuncAttributeMaxDynamicSharedMemorySize, CONV_SMEM);
        attr_set = true;
    }

    pool_kernel<<<dim3(C_, B_), 128>>>(x);
    mlp_kernel<<<B_, 64>>>(rw1, rb1, rw2, rb2);
    combine_kernel<<<dim3((WPERB/4 + 255)/256, B_), 256>>>(experts);
    conv_mma_kernel<<<dim3(25, 2, B_), 256, CONV_SMEM>>>(x, out);
}

// round 4
// speedup vs baseline: 3.2443x; 1.1448x over previous
#include <cuda_runtime.h>
#include <cuda_bf16.h>
#include <stdint.h>
#include <math.h>

#define B_   32
#define C_   256
#define HH   56
#define WW   56
#define E_   4
#define O_   256
#define HID_ 64
#define NPIX 3136
#define KDIM 2304
#define WPERB (O_*KDIM)
#define BK   32
#define PADK 36                       // padded k-stride (floats); 144B rows (16B-aligned)
#define NKT  (KDIM/BK)                // 72 k-tiles

// ---------------- device scratch (no runtime allocation) ----------------
__device__ float g_routing[B_*E_];
__device__ float g_pooled[B_*C_];
__device__ float g_combined[(size_t)B_*WPERB];   // tf32-rounded mixed weights

// ---------------- helpers ----------------
__device__ __forceinline__ uint32_t f2tf32(float f) {
    uint32_t u;
    asm("cvt.rna.tf32.f32 %0, %1;" : "=r"(u) : "f"(f));
    return u;
}

__device__ __forceinline__ void mma_tf32(float* d, const uint32_t* a, const uint32_t* b) {
    asm volatile(
        "mma.sync.aligned.m16n8k8.row.col.f32.tf32.tf32.f32 "
        "{%0,%1,%2,%3}, {%4,%5,%6,%7}, {%8,%9}, {%0,%1,%2,%3};"
        : "+f"(d[0]), "+f"(d[1]), "+f"(d[2]), "+f"(d[3])
        : "r"(a[0]), "r"(a[1]), "r"(a[2]), "r"(a[3]), "r"(b[0]), "r"(b[1]));
}

#define CP_ASYNC16(dst_u32, src_ptr) \
    asm volatile("cp.async.cg.shared.global [%0], [%1], 16;" :: "r"(dst_u32), "l"(src_ptr))
#define CP_COMMIT() asm volatile("cp.async.commit_group;" ::: "memory")
#define CP_WAIT0()  asm volatile("cp.async.wait_group 0;"  ::: "memory")

// ===========================================================================
// Kernel 1a: per-channel global average pool. grid (C_, B_), 128 threads.
// ===========================================================================
__global__ void __launch_bounds__(128) pool_kernel(const float* __restrict__ x) {
    const int c = blockIdx.x, b = blockIdx.y;
    const int tid = threadIdx.x;
    const float4* xc = (const float4*)(x + ((size_t)b*C_ + c)*NPIX);
    float s = 0.f;
    for (int i = tid; i < NPIX/4; i += 128) { float4 v = xc[i]; s += (v.x+v.y)+(v.z+v.w); }
    #pragma unroll
    for (int o = 16; o; o >>= 1) s += __shfl_xor_sync(0xffffffffu, s, o);
    __shared__ float ws[4];
    if ((tid & 31) == 0) ws[tid >> 5] = s;
    __syncthreads();
    if (tid == 0) g_pooled[b*C_ + c] = (ws[0]+ws[1]+ws[2]+ws[3]) * (1.0f/(float)NPIX);
}

// ===========================================================================
// Kernel 1b: MLP + softmax routing. grid B_, 64 threads.
// ===========================================================================
__global__ void __launch_bounds__(64) mlp_kernel(const float* __restrict__ rw1,
                                                 const float* __restrict__ rb1,
                                                 const float* __restrict__ rw2,
                                                 const float* __restrict__ rb2) {
    const int b = blockIdx.x, t = threadIdx.x;
    __shared__ float pl[C_];
    __shared__ float hid[HID_];
    __shared__ float logits[E_];
    for (int c = t; c < C_; c += 64) pl[c] = g_pooled[b*C_ + c];
    __syncthreads();
    {
        float s = rb1[t];
        const float* w = rw1 + t * C_;
        #pragma unroll 8
        for (int c = 0; c < C_; c++) s = fmaf(w[c], pl[c], s);
        hid[t] = fmaxf(s, 0.f);
    }
    __syncthreads();
    if (t < E_) {
        float s = rb2[t];
        const float* w = rw2 + t * HID_;
        #pragma unroll 8
        for (int h = 0; h < HID_; h++) s = fmaf(w[h], hid[h], s);
        logits[t] = s;
    }
    __syncthreads();
    if (t == 0) {
        float m = logits[0];
        #pragma unroll
        for (int e = 1; e < E_; e++) m = fmaxf(m, logits[e]);
        float ex[E_], sum = 0.f;
        #pragma unroll
        for (int e = 0; e < E_; e++) { ex[e] = expf(logits[e] - m); sum += ex[e]; }
        float inv = 1.0f / sum;
        #pragma unroll
        for (int e = 0; e < E_; e++) g_routing[b*E_ + e] = ex[e] * inv;
    }
}

// ===========================================================================
// Kernel 2: mix experts -> per-sample weights (tf32-rounded fp32).
// ===========================================================================
__global__ void __launch_bounds__(256) combine_kernel(const float* __restrict__ experts) {
    const int b = blockIdx.y;
    const int i = blockIdx.x * 256 + threadIdx.x;     // float4 index
    if (i >= WPERB/4) return;

    const float r0 = g_routing[b*E_+0], r1 = g_routing[b*E_+1];
    const float r2 = g_routing[b*E_+2], r3 = g_routing[b*E_+3];
    float4 a = ((const float4*)(experts + (size_t)0*WPERB))[i];
    float4 c = ((const float4*)(experts + (size_t)1*WPERB))[i];
    float4 d = ((const float4*)(experts + (size_t)2*WPERB))[i];
    float4 f = ((const float4*)(experts + (size_t)3*WPERB))[i];

    uint4 o;
    o.x = f2tf32(r0*a.x + r1*c.x + r2*d.x + r3*f.x);
    o.y = f2tf32(r0*a.y + r1*c.y + r2*d.y + r3*f.y);
    o.z = f2tf32(r0*a.z + r1*c.z + r2*d.z + r3*f.z);
    o.w = f2tf32(r0*a.w + r1*c.w + r2*d.w + r3*f.w);
    ((uint4*)g_combined)[(size_t)b*(WPERB/4) + i] = o;
}

// ===========================================================================
// Kernel 3: TF32 mma.sync implicit-GEMM conv.
//   CTA tile: 256(oc) x 128(px), K=2304 in 72 tiles of 32.
//   8 warps = 4(m) x 2(n); warp tile 64x64.
//   A (weights) -> smem via cp.async; B (im2col) LDG->reg->STS.128.
// ===========================================================================
__global__ void __launch_bounds__(256, 1) conv_mma_kernel(const float* __restrict__ x,
                                                          float* __restrict__ out) {
    extern __shared__ float sm[];
    float* As   = sm;                          // 2 * 256 * PADK
    float* Bs   = sm + 2*256*PADK;             // 2 * 128 * PADK
    int2*  ktab = (int2*)(sm + 2*256*PADK + 2*128*PADK);

    const int tid   = threadIdx.x;
    const int lane  = tid & 31;
    const int warp  = tid >> 5;
    const int nBase = blockIdx.x * 128;
    const int b     = blockIdx.y;

    const int g  = lane >> 2;      // 0..7
    const int tg = lane & 3;       // 0..3
    const int wm = warp >> 1;      // 0..3 (m)
    const int wn = warp & 1;       // 0..1 (n)

    // im2col k-table
    for (int k = tid; k < KDIM; k += 256) {
        int c = k / 9, rem = k - 9*c;
        int ky = rem / 3 - 1, kx = rem % 3 - 1;
        ktab[k] = make_int2(c*NPIX + ky*WW + kx, (ky << 16) | (kx & 0xffff));
    }
    __syncthreads();

    const float* Ab = g_combined + (size_t)b * WPERB;
    const float* xb = x + (size_t)b * C_ * NPIX;

    // B producer: thread -> pixel nl, k-half kh (16 consecutive k each)
    const int nl = tid & 127;
    const int kh = tid >> 7;              // 0 or 1
    const int n  = nBase + nl;
    const bool nvalid = (n < NPIX);
    const int ny = n / WW, nx = n - (n / WW) * WW;

    const uint32_t as_u32 = (uint32_t)__cvta_generic_to_shared(As);

    uint32_t breg[16];

    #define ISSUE_A(kt, s) do {                                                      \
        const int _k0 = (kt) * BK;                                                   \
        _Pragma("unroll")                                                            \
        for (int i = 0; i < 8; i++) {                                                \
            int idx = tid + i*256, row = idx >> 3, c4 = idx & 7;                     \
            uint32_t dst = as_u32 + (uint32_t)(((s)*256 + row)*PADK + c4*4)*4u;      \
            CP_ASYNC16(dst, Ab + (size_t)row*KDIM + _k0 + c4*4);                     \
        }                                                                            \
        CP_COMMIT();                                                                 \
    } while (0)

    #define LDG_B(kt) do {                                                           \
        const int _k0 = (kt) * BK + kh*16;                                           \
        _Pragma("unroll")                                                            \
        for (int i = 0; i < 16; i++) {                                               \
            int2 t = ktab[_k0 + i];                                                  \
            int ky = t.y >> 16, kx = (int)(short)(t.y & 0xffff);                     \
            float v = 0.f;                                                           \
            if (nvalid && (unsigned)(ny + ky) < 56u && (unsigned)(nx + kx) < 56u)    \
                v = __ldg(xb + t.x + n);                                             \
            breg[i] = f2tf32(v);                                                     \
        }                                                                            \
    } while (0)

    #define STS_B(s) do {                                                            \
        uint32_t* _d = (uint32_t*)(Bs + (s)*128*PADK + nl*PADK + kh*16);             \
        _Pragma("unroll")                                                            \
        for (int i = 0; i < 4; i++)                                                  \
            *(uint4*)(_d + i*4) = make_uint4(breg[i*4], breg[i*4+1],                 \
                                             breg[i*4+2], breg[i*4+3]);              \
    } while (0)

    float acc[4][8][4];
    #pragma unroll
    for (int mi = 0; mi < 4; mi++)
        #pragma unroll
        for (int ni = 0; ni < 8; ni++)
            #pragma unroll
            for (int q = 0; q < 4; q++) acc[mi][ni][q] = 0.f;

    // prologue
    ISSUE_A(0, 0);
    LDG_B(0);
    CP_WAIT0();
    STS_B(0);
    __syncthreads();

    for (int kt = 0; kt < NKT; kt++) {
        const int cur = kt & 1;
        if (kt + 1 < NKT) {
            ISSUE_A(kt + 1, cur ^ 1);
            LDG_B(kt + 1);
        }

        const uint32_t* Aw = (const uint32_t*)(As + cur*256*PADK + (wm*64 + g)*PADK);
        const uint32_t* Bw = (const uint32_t*)(Bs + cur*128*PADK + (wn*64 + g)*PADK);

        #pragma unroll
        for (int ks = 0; ks < 4; ks++) {
            const int kc = ks*8 + tg;
            uint32_t afr[4][4];
            #pragma unroll
            for (int mi = 0; mi < 4; mi++) {
                const uint32_t* p = Aw + mi*16*PADK + kc;
                afr[mi][0] = p[0];
                afr[mi][1] = p[8*PADK];
                afr[mi][2] = p[4];
                afr[mi][3] = p[8*PADK + 4];
            }
            uint32_t bfr[8][2];
            #pragma unroll
            for (int ni = 0; ni < 8; ni++) {
                const uint32_t* q = Bw + ni*8*PADK + kc;
                bfr[ni][0] = q[0];
                bfr[ni][1] = q[4];
            }
            #pragma unroll
            for (int mi = 0; mi < 4; mi++)
                #pragma unroll
                for (int ni = 0; ni < 8; ni++)
                    mma_tf32(acc[mi][ni], afr[mi], bfr[ni]);
        }

        if (kt + 1 < NKT) {
            CP_WAIT0();
            STS_B(cur ^ 1);
        }
        __syncthreads();
    }

    // ---- epilogue ----
    float* ob = out + (size_t)b * O_ * NPIX;
    #pragma unroll
    for (int mi = 0; mi < 4; mi++) {
        const int r0 = wm*64 + mi*16 + g;
        #pragma unroll
        for (int ni = 0; ni < 8; ni++) {
            const int cb = nBase + wn*64 + ni*8 + 2*tg;
            if (cb < NPIX) {
                *(float2*)(ob + (size_t)r0*NPIX + cb)     = make_float2(acc[mi][ni][0], acc[mi][ni][1]);
                *(float2*)(ob + (size_t)(r0+8)*NPIX + cb) = make_float2(acc[mi][ni][2], acc[mi][ni][3]);
            }
        }
    }
    #undef ISSUE_A
    #undef LDG_B
    #undef STS_B
}

#define CONV_SMEM ((2*256*PADK + 2*128*PADK)*4 + KDIM*8)   // 110592 + 18432 = 129024 B

// ===========================================================================
extern "C" void kernel_launch(void* const* d_in, const int* in_sizes, int n_in,
                              void* d_out, int out_size) {
    const float* x       = (const float*)d_in[0];
    const float* experts = (const float*)d_in[1];
    const float* rw1     = (const float*)d_in[2];
    const float* rb1     = (const float*)d_in[3];
    const float* rw2     = (const float*)d_in[4];
    const float* rb2     = (const float*)d_in[5];
    float* out           = (float*)d_out;

    static bool attr_set = false;
    if (!attr_set) {
        cudaFuncSetAttribute(conv_mma_kernel,
                             cudaFuncAttributeMaxDynamicSharedMemorySize, CONV_SMEM);
        attr_set = true;
    }

    pool_kernel<<<dim3(C_, B_), 128>>>(x);
    mlp_kernel<<<B_, 64>>>(rw1, rb1, rw2, rb2);
    combine_kernel<<<dim3((WPERB/4 + 255)/256, B_), 256>>>(experts);
    conv_mma_kernel<<<dim3(25, B_), 256, CONV_SMEM>>>(x, out);
}